// round 9
// baseline (speedup 1.0000x reference)
#include <cuda_runtime.h>

#define NB   64
#define SEQ  512
#define DIM  64
#define BIGF 1e30f
#define LOG2E 1.44269504088896340736f
#define LN2   0.69314718055994530942f
#define CANARY 0xFFC00001u
#define SLACK2 16

typedef unsigned long long u64;

// Scratch (static device globals — allocation-free per harness rules)
__device__ float g_D[(size_t)NB * SEQ * SEQ];   // 64 MiB, row-major per batch, pre-scaled by log2e
__device__ float g_x2[NB * SEQ];
__device__ float g_y2[NB * SEQ];

// ---------------------------------------------------------------------------
// f32x2 packed helpers (sm_103a FFMA2 path — PTX only, ptxas won't auto-fuse)
// ---------------------------------------------------------------------------
__device__ __forceinline__ u64 ffma2(u64 a, u64 b, u64 c) {
    u64 d;
    asm("fma.rn.f32x2 %0, %1, %2, %3;" : "=l"(d) : "l"(a), "l"(b), "l"(c));
    return d;
}
__device__ __forceinline__ u64 pack2(float lo, float hi) {
    u64 d;
    asm("mov.b64 %0, {%1, %2};" : "=l"(d) : "f"(lo), "f"(hi));
    return d;
}
__device__ __forceinline__ float2 unpack2(u64 v) {
    float2 r;
    asm("mov.b64 {%0, %1}, %2;" : "=f"(r.x), "=f"(r.y) : "l"(v));
    return r;
}
__device__ __forceinline__ float ex2(float x) {
    float r; asm("ex2.approx.ftz.f32 %0, %1;" : "=f"(r) : "f"(x)); return r;
}
__device__ __forceinline__ float lg2(float x) {
    float r; asm("lg2.approx.ftz.f32 %0, %1;" : "=f"(r) : "f"(x)); return r;
}

// ---------------------------------------------------------------------------
// Kernel 0: row norms. 8 threads per row, 32 rows per 256-thread block.
// ---------------------------------------------------------------------------
__global__ __launch_bounds__(256) void rownorm_kernel(const float* __restrict__ A, int which) {
    int row = blockIdx.x * 32 + (threadIdx.x >> 3);
    int l = threadIdx.x & 7;
    const float4* a = (const float4*)(A + (size_t)row * DIM);
    float4 v1 = __ldg(&a[l * 2]);
    float4 v2 = __ldg(&a[l * 2 + 1]);
    float s = v1.x*v1.x + v1.y*v1.y + v1.z*v1.z + v1.w*v1.w
            + v2.x*v2.x + v2.y*v2.y + v2.z*v2.z + v2.w*v2.w;
    s += __shfl_down_sync(0xffffffffu, s, 4);
    s += __shfl_down_sync(0xffffffffu, s, 2);
    s += __shfl_down_sync(0xffffffffu, s, 1);
    if (l == 0) {
        float* out = which ? g_y2 : g_x2;
        out[row] = s;
    }
}

// ---------------------------------------------------------------------------
// Kernel 1: pairwise squared distances with packed f32x2 FFMA2.
// D[b][i][j] = log2e * (x2[i] + y2[j] - 2 * dot(x_i, y_j))   (pre-scaled!)
// ---------------------------------------------------------------------------
#define BM 128
#define BN 128
#define BK 16
#define STRX 34
#define STRY 34

__global__ __launch_bounds__(256, 2) void pairdist_kernel(const float* __restrict__ X,
                                                          const float* __restrict__ Y) {
    __shared__ float Xs2[BM * STRX];
    __shared__ float Ys2[64 * STRY];

    int b  = blockIdx.z;
    int i0 = blockIdx.y * BM;
    int j0 = blockIdx.x * BN;
    const float* Xb = X + (size_t)b * SEQ * DIM + (size_t)i0 * DIM;
    const float* Yb = Y + (size_t)b * SEQ * DIM + (size_t)j0 * DIM;

    int tid = threadIdx.x;
    int tx = tid & 15;
    int ty = tid >> 4;

    u64 acc2[8][4];
#pragma unroll
    for (int r = 0; r < 8; r++)
#pragma unroll
        for (int c2 = 0; c2 < 4; c2++) acc2[r][c2] = 0ull;

    for (int k0 = 0; k0 < DIM; k0 += BK) {
        __syncthreads();
#pragma unroll
        for (int q = 0; q < 2; q++) {
            int idx = tid + q * 256;
            int r  = idx >> 2;
            int c4 = idx & 3;
            float4 xv = __ldg((const float4*)(Xb + (size_t)r * DIM + k0 + c4 * 4));
            float4 yv = __ldg((const float4*)(Yb + (size_t)r * DIM + k0 + c4 * 4));
            u64* xs = (u64*)&Xs2[r * STRX + c4 * 8];
            xs[0] = pack2(xv.x, xv.x);
            xs[1] = pack2(xv.y, xv.y);
            xs[2] = pack2(xv.z, xv.z);
            xs[3] = pack2(xv.w, xv.w);
            int pr   = (r & 15) + 16 * (r >> 5);
            int slot = (r >> 4) & 1;
            float* ys = &Ys2[pr * STRY + c4 * 8 + slot];
            ys[0] = yv.x; ys[2] = yv.y; ys[4] = yv.z; ys[6] = yv.w;
        }
        __syncthreads();

#pragma unroll
        for (int k = 0; k < BK; k++) {
            u64 bb[4];
#pragma unroll
            for (int c2 = 0; c2 < 4; c2++)
                bb[c2] = *(const u64*)&Ys2[(tx + 16 * c2) * STRY + k * 2];
#pragma unroll
            for (int r = 0; r < 8; r++) {
                u64 aa = *(const u64*)&Xs2[(ty + 16 * r) * STRX + k * 2];
#pragma unroll
                for (int c2 = 0; c2 < 4; c2++)
                    acc2[r][c2] = ffma2(aa, bb[c2], acc2[r][c2]);
            }
        }
    }

    float yn[8];
#pragma unroll
    for (int c = 0; c < 8; c++) yn[c] = g_y2[b * SEQ + j0 + tx + 16 * c];
    float* Db = g_D + (size_t)b * SEQ * SEQ;
#pragma unroll
    for (int r = 0; r < 8; r++) {
        int i = i0 + ty + 16 * r;
        float xn = g_x2[b * SEQ + i];
#pragma unroll
        for (int c2 = 0; c2 < 4; c2++) {
            float2 d2 = unpack2(acc2[r][c2]);
            int jA = j0 + tx + 16 * (2 * c2);
            int jB = j0 + tx + 16 * (2 * c2 + 1);
            Db[(size_t)i * SEQ + jA] = LOG2E * (xn + yn[2 * c2]     - 2.0f * d2.x);
            Db[(size_t)i * SEQ + jB] = LOG2E * (xn + yn[2 * c2 + 1] - 2.0f * d2.y);
        }
    }
}

// ---------------------------------------------------------------------------
// Kernel 2: soft-DTW wavefront. 1 CTA/batch, 8 warps, 2 rows/thread.
// Lane l of warp w owns rows i0 = 64w + 2l and i1 = i0 + 1.
// Beat idx processes diagonal p = 64w + idx: cells (i0, idx-2l), (i1, idx-2l-1).
// Dataflow (all registers):
//   row1: u = val0 (pre-update), a = diag1 (= val0 two beats ago), l = val1
//   row0: u = sh (= shfl_up(val1) / mailbox for lane 0), a = diag0 (= prev sh),
//         l = val0
// Lane 31 publishes row1 (strip bottom, row 64w+63) into its mailbox slot.
// Pure spin poll (best measured scheme) + one-time slack start at column 16.
// Warp-voted hard-min fast path: corr < 2^-22 when m1-mn >= 24 (log2 domain).
// ---------------------------------------------------------------------------
#define WARPS 8
#define TPB2 (WARPS * 32)   // 256

__global__ __launch_bounds__(TPB2) void softdtw_kernel(float* __restrict__ out) {
    int b    = blockIdx.x;
    int tid  = threadIdx.x;
    int w    = tid >> 5;
    int lane = tid & 31;

    __shared__ unsigned int bnd[(WARPS - 1) * SEQ];   // 14 KB mailboxes
    for (int k = tid; k < (WARPS - 1) * SEQ; k += TPB2) bnd[k] = CANARY;
    __syncthreads();

    int i0 = w * 64 + 2 * lane;
    const float4* r40 = (const float4*)(g_D + (size_t)b * SEQ * SEQ + (size_t)i0 * SEQ);
    const float4* r41 = r40 + SEQ / 4;
    float4 b0A = __ldg(r40), b0B = __ldg(r40 + 1);
    float4 b1A = __ldg(r41), b1B = __ldg(r41 + 1);
    int n0 = 2, n1 = 2;

    float val0 = BIGF, val1 = BIGF;
    float diag0 = (tid == 0) ? 0.0f : BIGF;   // (0,0): diagonal predecessor = 0
    float diag1 = BIGF;

    volatile unsigned int* rs = &bnd[(w > 0 ? w - 1 : 0) * SEQ];
    volatile unsigned int* ws = &bnd[(w < WARPS - 1 ? w : 0) * SEQ];

    // one-time slack start: producer must be SLACK2+63 beats ahead
    if (w > 0) {
        unsigned int v = rs[SLACK2];
        while (v == CANARY) v = rs[SLACK2];
    }

    for (int idx = 0; idx < SEQ + 63; ++idx) {
        // u for row0 = neighbor's val1 after previous beat
        float sh = __shfl_up_sync(0xffffffffu, val1, 1);
        if (w > 0) {
            if (idx < SEQ) {
                unsigned int v = rs[idx];              // broadcast LDS
                while (v == CANARY) v = rs[idx];       // pure spin (best measured)
                if (lane == 0) sh = __uint_as_float(v);
            }
        } else if (lane == 0) {
            sh = BIGF;                                 // global row 0: nothing above
        }

        int j0 = idx - 2 * lane;
        int j1 = j0 - 1;
        bool act0 = (j0 >= 0) && (j0 < SEQ);
        bool act1 = (j1 >= 0) && (j1 < SEQ);

        // row1 (uses current val0 = prev beat's row0 value)
        float u1 = val0, a1 = diag1, l1 = val1;
        float lo1 = fminf(u1, l1), hi1 = fmaxf(u1, l1);
        float mn1 = fminf(a1, lo1), m11 = fmaxf(a1, lo1);
        int mi1 = j1 & 3;
        float d1 = (mi1 == 0) ? b1A.x : (mi1 == 1) ? b1A.y : (mi1 == 2) ? b1A.z : b1A.w;

        // row0
        float u0 = sh, a0 = diag0, l0 = val0;
        float lo0 = fminf(u0, l0), hi0 = fmaxf(u0, l0);
        float mn0 = fminf(a0, lo0), m10 = fmaxf(a0, lo0);
        int mi0 = j0 & 3;
        float d0 = (mi0 == 0) ? b0A.x : (mi0 == 1) ? b0A.y : (mi0 == 2) ? b0A.z : b0A.w;

        float c0 = 0.0f, c1 = 0.0f;
        bool need = (act0 && (m10 - mn0 < 24.0f)) || (act1 && (m11 - mn1 < 24.0f));
        if (__any_sync(0xffffffffu, need)) {
            c0 = lg2(1.0f + ex2(mn0 - m10) + ex2(mn0 - hi0));
            c1 = lg2(1.0f + ex2(mn1 - m11) + ex2(mn1 - hi1));
        }
        float nv0 = d0 + mn0 - c0;
        float nv1 = d1 + mn1 - c1;

        // register rotation (pre-update values feed next beat's diag slots)
        diag1 = val0;
        diag0 = sh;

        if (act1) {
            val1 = nv1;
            if (mi1 == 3) {
                b1A = b1B;
                if (n1 < SEQ / 4) b1B = __ldg(r41 + n1);
                n1++;
            }
            if (lane == 31) {
                if (w < WARPS - 1)     ws[j1] = __float_as_uint(nv1);
                else if (j1 == SEQ - 1) out[b] = nv1 * LN2;
            }
        }
        if (act0) {
            val0 = nv0;
            if (mi0 == 3) {
                b0A = b0B;
                if (n0 < SEQ / 4) b0B = __ldg(r40 + n0);
                n0++;
            }
        }
    }
}

// ---------------------------------------------------------------------------
extern "C" void kernel_launch(void* const* d_in, const int* in_sizes, int n_in,
                              void* d_out, int out_size) {
    const float* x = (const float*)d_in[0];
    const float* y = (const float*)d_in[1];
    float* out = (float*)d_out;

    rownorm_kernel<<<NB * SEQ / 32, 256>>>(x, 0);
    rownorm_kernel<<<NB * SEQ / 32, 256>>>(y, 1);

    dim3 g(SEQ / BN, SEQ / BM, NB);
    pairdist_kernel<<<g, 256>>>(x, y);

    softdtw_kernel<<<NB, TPB2>>>(out);
}

// round 10
// speedup vs baseline: 1.0327x; 1.0327x over previous
#include <cuda_runtime.h>

#define NB   64
#define SEQ  512
#define DIM  64
#define BIGF 1e30f
#define LOG2E 1.44269504088896340736f
#define LN2   0.69314718055994530942f

typedef unsigned long long u64;

// Scratch (static device globals — allocation-free per harness rules)
__device__ float g_D[(size_t)NB * SEQ * SEQ];   // 64 MiB, row-major per batch, pre-scaled by log2e
__device__ float g_x2[NB * SEQ];
__device__ float g_y2[NB * SEQ];

// ---------------------------------------------------------------------------
// f32x2 packed helpers (sm_103a FFMA2 path — PTX only, ptxas won't auto-fuse)
// ---------------------------------------------------------------------------
__device__ __forceinline__ u64 ffma2(u64 a, u64 b, u64 c) {
    u64 d;
    asm("fma.rn.f32x2 %0, %1, %2, %3;" : "=l"(d) : "l"(a), "l"(b), "l"(c));
    return d;
}
__device__ __forceinline__ u64 pack2(float lo, float hi) {
    u64 d;
    asm("mov.b64 %0, {%1, %2};" : "=l"(d) : "f"(lo), "f"(hi));
    return d;
}
__device__ __forceinline__ float2 unpack2(u64 v) {
    float2 r;
    asm("mov.b64 {%0, %1}, %2;" : "=f"(r.x), "=f"(r.y) : "l"(v));
    return r;
}
__device__ __forceinline__ float ex2(float x) {
    float r; asm("ex2.approx.ftz.f32 %0, %1;" : "=f"(r) : "f"(x)); return r;
}
__device__ __forceinline__ float lg2(float x) {
    float r; asm("lg2.approx.ftz.f32 %0, %1;" : "=f"(r) : "f"(x)); return r;
}

// ---------------------------------------------------------------------------
// Kernel 0: row norms. 8 threads per row, 32 rows per 256-thread block.
// ---------------------------------------------------------------------------
__global__ __launch_bounds__(256) void rownorm_kernel(const float* __restrict__ A, int which) {
    int row = blockIdx.x * 32 + (threadIdx.x >> 3);
    int l = threadIdx.x & 7;
    const float4* a = (const float4*)(A + (size_t)row * DIM);
    float4 v1 = __ldg(&a[l * 2]);
    float4 v2 = __ldg(&a[l * 2 + 1]);
    float s = v1.x*v1.x + v1.y*v1.y + v1.z*v1.z + v1.w*v1.w
            + v2.x*v2.x + v2.y*v2.y + v2.z*v2.z + v2.w*v2.w;
    s += __shfl_down_sync(0xffffffffu, s, 4);
    s += __shfl_down_sync(0xffffffffu, s, 2);
    s += __shfl_down_sync(0xffffffffu, s, 1);
    if (l == 0) {
        float* out = which ? g_y2 : g_x2;
        out[row] = s;
    }
}

// ---------------------------------------------------------------------------
// Kernel 1: pairwise squared distances with packed f32x2 FFMA2.
// D[b][i][j] = log2e * (x2[i] + y2[j] - 2 * dot(x_i, y_j))   (pre-scaled!)
// ---------------------------------------------------------------------------
#define BM 128
#define BN 128
#define BK 16
#define STRX 34
#define STRY 34

__global__ __launch_bounds__(256, 2) void pairdist_kernel(const float* __restrict__ X,
                                                          const float* __restrict__ Y) {
    __shared__ float Xs2[BM * STRX];
    __shared__ float Ys2[64 * STRY];

    int b  = blockIdx.z;
    int i0 = blockIdx.y * BM;
    int j0 = blockIdx.x * BN;
    const float* Xb = X + (size_t)b * SEQ * DIM + (size_t)i0 * DIM;
    const float* Yb = Y + (size_t)b * SEQ * DIM + (size_t)j0 * DIM;

    int tid = threadIdx.x;
    int tx = tid & 15;
    int ty = tid >> 4;

    u64 acc2[8][4];
#pragma unroll
    for (int r = 0; r < 8; r++)
#pragma unroll
        for (int c2 = 0; c2 < 4; c2++) acc2[r][c2] = 0ull;

    for (int k0 = 0; k0 < DIM; k0 += BK) {
        __syncthreads();
#pragma unroll
        for (int q = 0; q < 2; q++) {
            int idx = tid + q * 256;
            int r  = idx >> 2;
            int c4 = idx & 3;
            float4 xv = __ldg((const float4*)(Xb + (size_t)r * DIM + k0 + c4 * 4));
            float4 yv = __ldg((const float4*)(Yb + (size_t)r * DIM + k0 + c4 * 4));
            u64* xs = (u64*)&Xs2[r * STRX + c4 * 8];
            xs[0] = pack2(xv.x, xv.x);
            xs[1] = pack2(xv.y, xv.y);
            xs[2] = pack2(xv.z, xv.z);
            xs[3] = pack2(xv.w, xv.w);
            int pr   = (r & 15) + 16 * (r >> 5);
            int slot = (r >> 4) & 1;
            float* ys = &Ys2[pr * STRY + c4 * 8 + slot];
            ys[0] = yv.x; ys[2] = yv.y; ys[4] = yv.z; ys[6] = yv.w;
        }
        __syncthreads();

#pragma unroll
        for (int k = 0; k < BK; k++) {
            u64 bb[4];
#pragma unroll
            for (int c2 = 0; c2 < 4; c2++)
                bb[c2] = *(const u64*)&Ys2[(tx + 16 * c2) * STRY + k * 2];
#pragma unroll
            for (int r = 0; r < 8; r++) {
                u64 aa = *(const u64*)&Xs2[(ty + 16 * r) * STRX + k * 2];
#pragma unroll
                for (int c2 = 0; c2 < 4; c2++)
                    acc2[r][c2] = ffma2(aa, bb[c2], acc2[r][c2]);
            }
        }
    }

    float yn[8];
#pragma unroll
    for (int c = 0; c < 8; c++) yn[c] = g_y2[b * SEQ + j0 + tx + 16 * c];
    float* Db = g_D + (size_t)b * SEQ * SEQ;
#pragma unroll
    for (int r = 0; r < 8; r++) {
        int i = i0 + ty + 16 * r;
        float xn = g_x2[b * SEQ + i];
#pragma unroll
        for (int c2 = 0; c2 < 4; c2++) {
            float2 d2 = unpack2(acc2[r][c2]);
            int jA = j0 + tx + 16 * (2 * c2);
            int jB = j0 + tx + 16 * (2 * c2 + 1);
            Db[(size_t)i * SEQ + jA] = LOG2E * (xn + yn[2 * c2]     - 2.0f * d2.x);
            Db[(size_t)i * SEQ + jB] = LOG2E * (xn + yn[2 * c2 + 1] - 2.0f * d2.y);
        }
    }
}

// ---------------------------------------------------------------------------
// Kernel 2: soft-DTW wavefront, BULK-SYNCHRONOUS with engineered slack.
// 1 CTA/batch, 16 warps, 1 row/thread (R2 dataflow), but warp w runs with a
// 64-beat skew (not the natural 32): warp w's local beat idx executes at
// global beat g = idx + 64w. The boundary value warp w reads at local idx was
// published by warp w-1 at global beat g-33. With __syncthreads() every 32
// beats, g-33 is ALWAYS in a strictly earlier phase -> the barrier proves the
// smem value is visible. No spin, no canary, no volatile, no polling.
//   u = shfl_up(val) (lane>0) or bnd[w-1][idx] (lane 0);
//   a = previous beat's u (register); l = own val (register).
// Lane 31 publishes its val per active beat (plain STS; BAR drains STS).
// Warp-voted hard-min fast path: corr < 2^-22 when m1-mn >= 24 (log2 domain).
// Makespan: 15*64 + 543 = 1503 beats = 47 phases of 32.
// ---------------------------------------------------------------------------
#define LOCAL_BEATS (SEQ + 31)                 // 543
#define PHASE 32
#define GBEATS (15 * 64 + LOCAL_BEATS)         // 1503
#define PHASES ((GBEATS + PHASE - 1) / PHASE)  // 47

__global__ __launch_bounds__(SEQ) void softdtw_kernel(float* __restrict__ out) {
    int b    = blockIdx.x;
    int tid  = threadIdx.x;
    int w    = tid >> 5;
    int lane = tid & 31;

    __shared__ unsigned int bnd[15 * SEQ];     // 30 KB boundary history (warps 0..14)

    int i = tid;
    const float4* row4 = (const float4*)(g_D + (size_t)b * SEQ * SEQ + (size_t)i * SEQ);
    float4 bufA = __ldg(row4);
    float4 bufB = __ldg(row4 + 1);
    float4 bufC = __ldg(row4 + 2);
    int nxt = 3;

    float val  = BIGF;
    float areg = (i == 0) ? 0.0f : BIGF;       // (0,0): diagonal predecessor = 0

    const unsigned int* rs = &bnd[(w > 0 ? w - 1 : 0) * SEQ];
    unsigned int*       ws = &bnd[(w < 15 ? w : 0) * SEQ];

    int delay = 64 * w;                        // engineered skew

    for (int ph = 0; ph < PHASES; ++ph) {
        int base = ph * PHASE - delay;
#pragma unroll 4
        for (int s = 0; s < PHASE; ++s) {
            int idx = base + s;                // warp-local beat
            if ((unsigned)idx < (unsigned)LOCAL_BEATS) {   // warp-uniform branch
                float sh = __shfl_up_sync(0xffffffffu, val, 1);
                float u = sh;
                if (w > 0) {
                    if (idx < SEQ) {
                        unsigned int v = rs[idx];          // guaranteed by BAR
                        if (lane == 0) u = __uint_as_float(v);
                    }
                } else if (lane == 0) {
                    u = BIGF;                              // global row 0
                }

                int j = idx - lane;
                bool act = (j >= 0) && (j < SEQ);

                float a = areg, l = val;
                float lo = fminf(u, l), hi = fmaxf(u, l);
                float mn = fminf(a, lo), m1 = fmaxf(a, lo);

                int m = j & 3;
                float d = (m == 0) ? bufA.x : (m == 1) ? bufA.y
                        : (m == 2) ? bufA.z : bufA.w;

                float corr = 0.0f;
                bool need = act && (m1 - mn < 24.0f);
                if (__any_sync(0xffffffffu, need)) {
                    float sum = 1.0f + ex2(mn - m1) + ex2(mn - hi);
                    corr = lg2(sum);
                }
                float nv = d + mn - corr;
                areg = u;

                if (act) {
                    val = nv;
                    if (m == 3) {
                        bufA = bufB; bufB = bufC;
                        if (nxt < SEQ / 4) bufC = __ldg(row4 + nxt);
                        nxt++;
                    }
                    if (lane == 31) {
                        if (w < 15)            ws[j]  = __float_as_uint(nv);
                        else if (j == SEQ - 1) out[b] = nv * LN2;
                    }
                }
            }
        }
        __syncthreads();
    }
}

// ---------------------------------------------------------------------------
extern "C" void kernel_launch(void* const* d_in, const int* in_sizes, int n_in,
                              void* d_out, int out_size) {
    const float* x = (const float*)d_in[0];
    const float* y = (const float*)d_in[1];
    float* out = (float*)d_out;

    rownorm_kernel<<<NB * SEQ / 32, 256>>>(x, 0);
    rownorm_kernel<<<NB * SEQ / 32, 256>>>(y, 1);

    dim3 g(SEQ / BN, SEQ / BM, NB);
    pairdist_kernel<<<g, 256>>>(x, y);

    softdtw_kernel<<<NB, SEQ>>>(out);
}

// round 11
// speedup vs baseline: 1.1906x; 1.1530x over previous
#include <cuda_runtime.h>

#define NB   64
#define SEQ  512
#define DIM  64
#define BIGF 1e30f
#define LOG2E 1.44269504088896340736f
#define LN2   0.69314718055994530942f

typedef unsigned long long u64;

// Scratch (static device globals — allocation-free per harness rules)
// TRANSPOSED layout: g_D[b][j][i]  (column j contiguous in i)
__device__ float g_D[(size_t)NB * SEQ * SEQ];
__device__ float g_x2[NB * SEQ];
__device__ float g_y2[NB * SEQ];

// ---------------------------------------------------------------------------
// f32x2 packed helpers (sm_103a FFMA2 path — PTX only, ptxas won't auto-fuse)
// ---------------------------------------------------------------------------
__device__ __forceinline__ u64 ffma2(u64 a, u64 b, u64 c) {
    u64 d;
    asm("fma.rn.f32x2 %0, %1, %2, %3;" : "=l"(d) : "l"(a), "l"(b), "l"(c));
    return d;
}
__device__ __forceinline__ u64 pack2(float lo, float hi) {
    u64 d;
    asm("mov.b64 %0, {%1, %2};" : "=l"(d) : "f"(lo), "f"(hi));
    return d;
}
__device__ __forceinline__ float2 unpack2(u64 v) {
    float2 r;
    asm("mov.b64 {%0, %1}, %2;" : "=f"(r.x), "=f"(r.y) : "l"(v));
    return r;
}
__device__ __forceinline__ float ex2(float x) {
    float r; asm("ex2.approx.ftz.f32 %0, %1;" : "=f"(r) : "f"(x)); return r;
}
__device__ __forceinline__ float lg2(float x) {
    float r; asm("lg2.approx.ftz.f32 %0, %1;" : "=f"(r) : "f"(x)); return r;
}

// ---------------------------------------------------------------------------
// Kernel 0: row norms. 8 threads per row, 32 rows per 256-thread block.
// ---------------------------------------------------------------------------
__global__ __launch_bounds__(256) void rownorm_kernel(const float* __restrict__ A, int which) {
    int row = blockIdx.x * 32 + (threadIdx.x >> 3);
    int l = threadIdx.x & 7;
    const float4* a = (const float4*)(A + (size_t)row * DIM);
    float4 v1 = __ldg(&a[l * 2]);
    float4 v2 = __ldg(&a[l * 2 + 1]);
    float s = v1.x*v1.x + v1.y*v1.y + v1.z*v1.z + v1.w*v1.w
            + v2.x*v2.x + v2.y*v2.y + v2.z*v2.z + v2.w*v2.w;
    s += __shfl_down_sync(0xffffffffu, s, 4);
    s += __shfl_down_sync(0xffffffffu, s, 2);
    s += __shfl_down_sync(0xffffffffu, s, 1);
    if (l == 0) {
        float* out = which ? g_y2 : g_x2;
        out[row] = s;
    }
}

// ---------------------------------------------------------------------------
// Kernel 1: pairwise squared distances with packed f32x2 FFMA2.
// Writes TRANSPOSED + log2e-scaled: D_t[b][j][i] = log2e*(x2[i]+y2[j]-2*dot).
// Epilogue: smem-staged transpose (4 chunks of 32 columns) -> coalesced STG.
// ---------------------------------------------------------------------------
#define BM 128
#define BN 128
#define BK 16
#define STRX 34
#define STRY 34
#define TPAD 132   // transpose tile stride (words): keeps float4 align, spreads banks

__global__ __launch_bounds__(256, 2) void pairdist_kernel(const float* __restrict__ X,
                                                          const float* __restrict__ Y) {
    __shared__ __align__(16) float Xs2[BM * STRX];   // 17.4 KB (reused as transpose tile)
    __shared__ float Ys2[64 * STRY];                 //  8.7 KB

    int b  = blockIdx.z;
    int i0 = blockIdx.y * BM;
    int j0 = blockIdx.x * BN;
    const float* Xb = X + (size_t)b * SEQ * DIM + (size_t)i0 * DIM;
    const float* Yb = Y + (size_t)b * SEQ * DIM + (size_t)j0 * DIM;

    int tid = threadIdx.x;
    int tx = tid & 15;
    int ty = tid >> 4;

    u64 acc2[8][4];
#pragma unroll
    for (int r = 0; r < 8; r++)
#pragma unroll
        for (int c2 = 0; c2 < 4; c2++) acc2[r][c2] = 0ull;

    for (int k0 = 0; k0 < DIM; k0 += BK) {
        __syncthreads();
#pragma unroll
        for (int q = 0; q < 2; q++) {
            int idx = tid + q * 256;
            int r  = idx >> 2;
            int c4 = idx & 3;
            float4 xv = __ldg((const float4*)(Xb + (size_t)r * DIM + k0 + c4 * 4));
            float4 yv = __ldg((const float4*)(Yb + (size_t)r * DIM + k0 + c4 * 4));
            u64* xs = (u64*)&Xs2[r * STRX + c4 * 8];
            xs[0] = pack2(xv.x, xv.x);
            xs[1] = pack2(xv.y, xv.y);
            xs[2] = pack2(xv.z, xv.z);
            xs[3] = pack2(xv.w, xv.w);
            int pr   = (r & 15) + 16 * (r >> 5);
            int slot = (r >> 4) & 1;
            float* ys = &Ys2[pr * STRY + c4 * 8 + slot];
            ys[0] = yv.x; ys[2] = yv.y; ys[4] = yv.z; ys[6] = yv.w;
        }
        __syncthreads();

#pragma unroll
        for (int k = 0; k < BK; k++) {
            u64 bb[4];
#pragma unroll
            for (int c2 = 0; c2 < 4; c2++)
                bb[c2] = *(const u64*)&Ys2[(tx + 16 * c2) * STRY + k * 2];
#pragma unroll
            for (int r = 0; r < 8; r++) {
                u64 aa = *(const u64*)&Xs2[(ty + 16 * r) * STRX + k * 2];
#pragma unroll
                for (int c2 = 0; c2 < 4; c2++)
                    acc2[r][c2] = ffma2(aa, bb[c2], acc2[r][c2]);
            }
        }
    }

    // -------- epilogue: finalize + transpose via smem + coalesced store -----
    float yn[8];
#pragma unroll
    for (int c = 0; c < 8; c++) yn[c] = g_y2[b * SEQ + j0 + tx + 16 * c];
    float xnr[8];
#pragma unroll
    for (int r = 0; r < 8; r++) xnr[r] = g_x2[b * SEQ + i0 + ty + 16 * r];

    float* Dt = g_D + (size_t)b * SEQ * SEQ;
    float* T  = Xs2;   // alias: 32*TPAD = 4224 floats <= 4352

    __syncthreads();   // everyone done reading Xs2 in the k-loop
#pragma unroll
    for (int q = 0; q < 4; q++) {            // chunk: 32 columns j0+32q + [0,32)
#pragma unroll
        for (int r = 0; r < 8; r++) {
            int ii = ty + 16 * r;
            float2 d2 = unpack2(acc2[r][q]);
            T[tx * TPAD + ii]        = LOG2E * (xnr[r] + yn[2 * q]     - 2.0f * d2.x);
            T[(tx + 16) * TPAD + ii] = LOG2E * (xnr[r] + yn[2 * q + 1] - 2.0f * d2.y);
        }
        __syncthreads();
#pragma unroll
        for (int v = 0; v < 4; v++) {
            int jj2 = tid >> 3;
            int ii2 = (tid & 7) * 16 + v * 4;
            float4 t = *(float4*)&T[jj2 * TPAD + ii2];
            *(float4*)&Dt[(size_t)(j0 + 32 * q + jj2) * SEQ + i0 + ii2] = t;
        }
        __syncthreads();
    }
}

// ---------------------------------------------------------------------------
// Kernel 2: soft-DTW, SYNC-FREE. One warp per batch (grid=64, block=32).
// Lane t owns rows 16t..16t+15. Beat idx: lane t computes ALL 16 cells of
// column j = idx - t (valid: cell (i+1,j) deps are (i,j) same beat [reg chain],
// (i,j-1) & (i+1,j-1) prev beat [regs]). Lane boundary: exactly one shfl_up of
// the bottom-row value per beat (neighbor is 1 beat ahead -> value is exact).
// No smem, no barriers, no mailboxes.
// D is transposed: column j = 16 contiguous floats per lane; 3-column register
// ring gives ~3-beat (>latency) prefetch distance.
// Softmin correction (log2 domain, D pre-scaled): fired only when
// m1-mn < 10 (error <= 0.0028/cell, accumulated ~3e-5 rel — well under 1e-3).
// ---------------------------------------------------------------------------
__global__ __launch_bounds__(32) void softdtw_kernel(float* __restrict__ out) {
    int b    = blockIdx.x;
    int lane = threadIdx.x;

    const float* Dt = g_D + (size_t)b * SEQ * SEQ;   // [j][i]
    const float4* colbase = (const float4*)(Dt + lane * 16);   // + j*(SEQ/4) float4s

    float val[16];
#pragma unroll
    for (int r = 0; r < 16; r++) val[r] = BIGF;
    float shp = (lane == 0) ? 0.0f : BIGF;   // R(16t-1, j-1); lane0 idx0 -> R(-1,-1)=0

    // 3-column prefetch ring
    float4 ring[3][4];
#pragma unroll
    for (int s = 0; s < 3; s++)
#pragma unroll
        for (int q = 0; q < 4; q++)
            ring[s][q] = __ldg(colbase + (size_t)s * (SEQ / 4) + q);

    for (int idx = 0; idx < SEQ + 31; ++idx) {
        float sh = __shfl_up_sync(0xffffffffu, val[15], 1);
        if (lane == 0) sh = BIGF;            // no row above global row 0

        int j = idx - lane;
        if (j >= 0 && j < SEQ) {
            int s = j % 3;
            float4 c0 = ring[s][0], c1 = ring[s][1], c2 = ring[s][2], c3 = ring[s][3];
            int jt = j + 3;
            if (jt < SEQ) {                  // prefetch 3 columns ahead into freed slot
#pragma unroll
                for (int q = 0; q < 4; q++)
                    ring[s][q] = __ldg(colbase + (size_t)jt * (SEQ / 4) + q);
            }

            const float dv[16] = { c0.x, c0.y, c0.z, c0.w,  c1.x, c1.y, c1.z, c1.w,
                                   c2.x, c2.y, c2.z, c2.w,  c3.x, c3.y, c3.z, c3.w };

            float a = shp;                   // R(row-1, j-1)
            float u = sh;                    // R(row-1, j)
#pragma unroll
            for (int r = 0; r < 16; r++) {
                float l  = val[r];           // R(row, j-1)
                float lo = fminf(u, l), hi = fmaxf(u, l);
                float mn = fminf(a, lo), m1 = fmaxf(a, lo);
                float nv = dv[r] + mn;
                if (m1 - mn < 10.0f)
                    nv -= lg2(1.0f + ex2(mn - m1) + ex2(mn - hi));
                a = l;                       // next cell's diag = old val[r]
                u = nv;                      // next cell's up
                val[r] = nv;
            }
            if (lane == 31 && j == SEQ - 1) out[b] = val[15] * LN2;
        }
        shp = sh;                            // rotate boundary diag
    }
}

// ---------------------------------------------------------------------------
extern "C" void kernel_launch(void* const* d_in, const int* in_sizes, int n_in,
                              void* d_out, int out_size) {
    const float* x = (const float*)d_in[0];
    const float* y = (const float*)d_in[1];
    float* out = (float*)d_out;

    rownorm_kernel<<<NB * SEQ / 32, 256>>>(x, 0);
    rownorm_kernel<<<NB * SEQ / 32, 256>>>(y, 1);

    dim3 g(SEQ / BN, SEQ / BM, NB);
    pairdist_kernel<<<g, 256>>>(x, y);

    softdtw_kernel<<<NB, 32>>>(out);
}

// round 12
// speedup vs baseline: 1.3770x; 1.1565x over previous
#include <cuda_runtime.h>

#define NB   64
#define SEQ  512
#define DIM  64
#define BIGF 1e30f
#define LOG2E 1.44269504088896340736f
#define LN2   0.69314718055994530942f

typedef unsigned long long u64;

// Scratch (static device globals — allocation-free per harness rules)
// TRANSPOSED layout: g_D[b][j][i]  (column j contiguous in i)
__device__ float g_D[(size_t)NB * SEQ * SEQ];
__device__ float g_x2[NB * SEQ];
__device__ float g_y2[NB * SEQ];

// ---------------------------------------------------------------------------
// f32x2 packed helpers (sm_103a FFMA2 path — PTX only, ptxas won't auto-fuse)
// ---------------------------------------------------------------------------
__device__ __forceinline__ u64 ffma2(u64 a, u64 b, u64 c) {
    u64 d;
    asm("fma.rn.f32x2 %0, %1, %2, %3;" : "=l"(d) : "l"(a), "l"(b), "l"(c));
    return d;
}
__device__ __forceinline__ u64 pack2(float lo, float hi) {
    u64 d;
    asm("mov.b64 %0, {%1, %2};" : "=l"(d) : "f"(lo), "f"(hi));
    return d;
}
__device__ __forceinline__ float2 unpack2(u64 v) {
    float2 r;
    asm("mov.b64 {%0, %1}, %2;" : "=f"(r.x), "=f"(r.y) : "l"(v));
    return r;
}

// Predicated softmin correction, NO BSSY/branch: corr = lg2(1 + 2^(mn-m1) + 2^(mn-hi))
// computed only when gap g = m1-mn < 8 (else corr stays 0; dropped mass <= 2^-8).
__device__ __forceinline__ float softmin_corr(float g, float e1, float e2) {
    float corr = 0.0f;
    asm("{\n\t"
        ".reg .pred p;\n\t"
        ".reg .f32 t1, t2, t3;\n\t"
        "setp.lt.ftz.f32 p, %1, 0f41000000;\n\t"   // g < 8.0f
        "@p ex2.approx.ftz.f32 t1, %2;\n\t"
        "@p ex2.approx.ftz.f32 t2, %3;\n\t"
        "@p add.ftz.f32 t3, t1, t2;\n\t"
        "@p add.ftz.f32 t3, t3, 0f3F800000;\n\t"   // + 1.0f
        "@p lg2.approx.ftz.f32 %0, t3;\n\t"
        "}" : "+f"(corr) : "f"(g), "f"(e1), "f"(e2));
    return corr;
}

// ---------------------------------------------------------------------------
// Kernel 0: row norms. 8 threads per row, 32 rows per 256-thread block.
// ---------------------------------------------------------------------------
__global__ __launch_bounds__(256) void rownorm_kernel(const float* __restrict__ A, int which) {
    int row = blockIdx.x * 32 + (threadIdx.x >> 3);
    int l = threadIdx.x & 7;
    const float4* a = (const float4*)(A + (size_t)row * DIM);
    float4 v1 = __ldg(&a[l * 2]);
    float4 v2 = __ldg(&a[l * 2 + 1]);
    float s = v1.x*v1.x + v1.y*v1.y + v1.z*v1.z + v1.w*v1.w
            + v2.x*v2.x + v2.y*v2.y + v2.z*v2.z + v2.w*v2.w;
    s += __shfl_down_sync(0xffffffffu, s, 4);
    s += __shfl_down_sync(0xffffffffu, s, 2);
    s += __shfl_down_sync(0xffffffffu, s, 1);
    if (l == 0) {
        float* out = which ? g_y2 : g_x2;
        out[row] = s;
    }
}

// ---------------------------------------------------------------------------
// Kernel 1: pairwise squared distances with packed f32x2 FFMA2.
// Writes TRANSPOSED + log2e-scaled: D_t[b][j][i] = log2e*(x2[i]+y2[j]-2*dot).
// Epilogue: smem-staged transpose (4 chunks of 32 columns) -> coalesced STG.
// ---------------------------------------------------------------------------
#define BM 128
#define BN 128
#define BK 16
#define STRX 34
#define STRY 34
#define TPAD 132

__global__ __launch_bounds__(256, 2) void pairdist_kernel(const float* __restrict__ X,
                                                          const float* __restrict__ Y) {
    __shared__ __align__(16) float Xs2[BM * STRX];
    __shared__ float Ys2[64 * STRY];

    int b  = blockIdx.z;
    int i0 = blockIdx.y * BM;
    int j0 = blockIdx.x * BN;
    const float* Xb = X + (size_t)b * SEQ * DIM + (size_t)i0 * DIM;
    const float* Yb = Y + (size_t)b * SEQ * DIM + (size_t)j0 * DIM;

    int tid = threadIdx.x;
    int tx = tid & 15;
    int ty = tid >> 4;

    u64 acc2[8][4];
#pragma unroll
    for (int r = 0; r < 8; r++)
#pragma unroll
        for (int c2 = 0; c2 < 4; c2++) acc2[r][c2] = 0ull;

    for (int k0 = 0; k0 < DIM; k0 += BK) {
        __syncthreads();
#pragma unroll
        for (int q = 0; q < 2; q++) {
            int idx = tid + q * 256;
            int r  = idx >> 2;
            int c4 = idx & 3;
            float4 xv = __ldg((const float4*)(Xb + (size_t)r * DIM + k0 + c4 * 4));
            float4 yv = __ldg((const float4*)(Yb + (size_t)r * DIM + k0 + c4 * 4));
            u64* xs = (u64*)&Xs2[r * STRX + c4 * 8];
            xs[0] = pack2(xv.x, xv.x);
            xs[1] = pack2(xv.y, xv.y);
            xs[2] = pack2(xv.z, xv.z);
            xs[3] = pack2(xv.w, xv.w);
            int pr   = (r & 15) + 16 * (r >> 5);
            int slot = (r >> 4) & 1;
            float* ys = &Ys2[pr * STRY + c4 * 8 + slot];
            ys[0] = yv.x; ys[2] = yv.y; ys[4] = yv.z; ys[6] = yv.w;
        }
        __syncthreads();

#pragma unroll
        for (int k = 0; k < BK; k++) {
            u64 bb[4];
#pragma unroll
            for (int c2 = 0; c2 < 4; c2++)
                bb[c2] = *(const u64*)&Ys2[(tx + 16 * c2) * STRY + k * 2];
#pragma unroll
            for (int r = 0; r < 8; r++) {
                u64 aa = *(const u64*)&Xs2[(ty + 16 * r) * STRX + k * 2];
#pragma unroll
                for (int c2 = 0; c2 < 4; c2++)
                    acc2[r][c2] = ffma2(aa, bb[c2], acc2[r][c2]);
            }
        }
    }

    // -------- epilogue: finalize + transpose via smem + coalesced store -----
    float yn[8];
#pragma unroll
    for (int c = 0; c < 8; c++) yn[c] = g_y2[b * SEQ + j0 + tx + 16 * c];
    float xnr[8];
#pragma unroll
    for (int r = 0; r < 8; r++) xnr[r] = g_x2[b * SEQ + i0 + ty + 16 * r];

    float* Dt = g_D + (size_t)b * SEQ * SEQ;
    float* T  = Xs2;

    __syncthreads();
#pragma unroll
    for (int q = 0; q < 4; q++) {
#pragma unroll
        for (int r = 0; r < 8; r++) {
            int ii = ty + 16 * r;
            float2 d2 = unpack2(acc2[r][q]);
            T[tx * TPAD + ii]        = LOG2E * (xnr[r] + yn[2 * q]     - 2.0f * d2.x);
            T[(tx + 16) * TPAD + ii] = LOG2E * (xnr[r] + yn[2 * q + 1] - 2.0f * d2.y);
        }
        __syncthreads();
#pragma unroll
        for (int v = 0; v < 4; v++) {
            int jj2 = tid >> 3;
            int ii2 = (tid & 7) * 16 + v * 4;
            float4 t = *(float4*)&T[jj2 * TPAD + ii2];
            *(float4*)&Dt[(size_t)(j0 + 32 * q + jj2) * SEQ + i0 + ii2] = t;
        }
        __syncthreads();
    }
}

// ---------------------------------------------------------------------------
// Kernel 2: soft-DTW, SYNC-FREE, one warp per batch. Lane t owns rows
// 16t..16t+15; beat idx computes all 16 cells of column j = idx - t.
// One shfl_up per beat (neighbor's bottom row, exact by the 1-beat skew).
// FIXES vs R11:
//   * 3-stage column pipeline cur/nA/nB with EXPLICIT rotation (constant
//     indices only -> registers, no local memory; ~90 regs, 1 warp so fine)
//   * softmin correction via setp + @p predicated MUFUs (no BSSY/BSYNC, no
//     divergence); threshold 8 log2-units (dropped mass <= 2^-8 per cell,
//     <= 6e-5 relative accumulated — tolerance is 1e-3)
// ---------------------------------------------------------------------------
#define CELL(DVAL)                                             \
    {                                                          \
        float l  = val[_r];                                    \
        float lo = fminf(u, l), hi = fmaxf(u, l);              \
        float mn = fminf(a, lo), m1 = fmaxf(a, lo);            \
        float corr = softmin_corr(m1 - mn, mn - m1, mn - hi);  \
        float nv = (DVAL) + mn - corr;                         \
        a = l; u = nv; val[_r] = nv; _r++;                     \
    }

__global__ __launch_bounds__(32, 1) void softdtw_kernel(float* __restrict__ out) {
    int b    = blockIdx.x;
    int lane = threadIdx.x;

    const float4* colbase = (const float4*)(g_D + (size_t)b * SEQ * SEQ + lane * 16);
    const int CSTRIDE = SEQ / 4;   // float4s per column

    float val[16];
#pragma unroll
    for (int r = 0; r < 16; r++) val[r] = BIGF;
    float shp = (lane == 0) ? 0.0f : BIGF;   // R(16t-1, j-1); lane0 idx0 -> R(-1,-1)=0

    // 3-stage column pipeline: cur = col j, nA = col j+1, nB = col j+2
    float4 cur0 = __ldg(colbase + 0), cur1 = __ldg(colbase + 1),
           cur2 = __ldg(colbase + 2), cur3 = __ldg(colbase + 3);
    float4 nA0 = __ldg(colbase + CSTRIDE + 0), nA1 = __ldg(colbase + CSTRIDE + 1),
           nA2 = __ldg(colbase + CSTRIDE + 2), nA3 = __ldg(colbase + CSTRIDE + 3);
    float4 nB0 = __ldg(colbase + 2 * CSTRIDE + 0), nB1 = __ldg(colbase + 2 * CSTRIDE + 1),
           nB2 = __ldg(colbase + 2 * CSTRIDE + 2), nB3 = __ldg(colbase + 2 * CSTRIDE + 3);

    for (int idx = 0; idx < SEQ + 31; ++idx) {
        float sh = __shfl_up_sync(0xffffffffu, val[15], 1);
        if (lane == 0) sh = BIGF;            // no row above global row 0

        int j = idx - lane;
        if (j >= 0 && j < SEQ) {
            float a = shp;                   // R(row-1, j-1)
            float u = sh;                    // R(row-1, j)
            int _r = 0;
            CELL(cur0.x) CELL(cur0.y) CELL(cur0.z) CELL(cur0.w)
            CELL(cur1.x) CELL(cur1.y) CELL(cur1.z) CELL(cur1.w)
            CELL(cur2.x) CELL(cur2.y) CELL(cur2.z) CELL(cur2.w)
            CELL(cur3.x) CELL(cur3.y) CELL(cur3.z) CELL(cur3.w)

            if (lane == 31 && j == SEQ - 1) out[b] = u * LN2;

            // rotate pipeline + prefetch column j+3 (registers only)
            cur0 = nA0; cur1 = nA1; cur2 = nA2; cur3 = nA3;
            nA0 = nB0; nA1 = nB1; nA2 = nB2; nA3 = nB3;
            int jt = j + 3;
            if (jt < SEQ) {
                const float4* p = colbase + (size_t)jt * CSTRIDE;
                nB0 = __ldg(p + 0); nB1 = __ldg(p + 1);
                nB2 = __ldg(p + 2); nB3 = __ldg(p + 3);
            }
        }
        shp = sh;                            // rotate boundary diag
    }
}

// ---------------------------------------------------------------------------
extern "C" void kernel_launch(void* const* d_in, const int* in_sizes, int n_in,
                              void* d_out, int out_size) {
    const float* x = (const float*)d_in[0];
    const float* y = (const float*)d_in[1];
    float* out = (float*)d_out;

    rownorm_kernel<<<NB * SEQ / 32, 256>>>(x, 0);
    rownorm_kernel<<<NB * SEQ / 32, 256>>>(y, 1);

    dim3 g(SEQ / BN, SEQ / BM, NB);
    pairdist_kernel<<<g, 256>>>(x, y);

    softdtw_kernel<<<NB, 32>>>(out);
}

// round 16
// speedup vs baseline: 1.9336x; 1.4042x over previous
#include <cuda_runtime.h>

#define NB   64
#define SEQ  512
#define DIM  64
#define BIGF 1e30f
#define LOG2E 1.44269504088896340736f
#define LN2   0.69314718055994530942f

typedef unsigned long long u64;

// Scratch (static device globals — allocation-free per harness rules)
// TRANSPOSED layout: g_D[b][j][i]  (column j contiguous in i)
__device__ float g_D[(size_t)NB * SEQ * SEQ];
__device__ float g_x2[NB * SEQ];
__device__ float g_y2[NB * SEQ];

// ---------------------------------------------------------------------------
// f32x2 packed helpers (sm_103a FFMA2 path — PTX only, ptxas won't auto-fuse)
// ---------------------------------------------------------------------------
__device__ __forceinline__ u64 ffma2(u64 a, u64 b, u64 c) {
    u64 d;
    asm("fma.rn.f32x2 %0, %1, %2, %3;" : "=l"(d) : "l"(a), "l"(b), "l"(c));
    return d;
}
__device__ __forceinline__ u64 pack2(float lo, float hi) {
    u64 d;
    asm("mov.b64 %0, {%1, %2};" : "=l"(d) : "f"(lo), "f"(hi));
    return d;
}
__device__ __forceinline__ float2 unpack2(u64 v) {
    float2 r;
    asm("mov.b64 {%0, %1}, %2;" : "=f"(r.x), "=f"(r.y) : "l"(v));
    return r;
}
__device__ __forceinline__ float ex2(float x) {
    float r; asm("ex2.approx.ftz.f32 %0, %1;" : "=f"(r) : "f"(x)); return r;
}
__device__ __forceinline__ float lg2(float x) {
    float r; asm("lg2.approx.ftz.f32 %0, %1;" : "=f"(r) : "f"(x)); return r;
}

// ---------------------------------------------------------------------------
// Kernel 0: row norms. 8 threads per row, 32 rows per 256-thread block.
// ---------------------------------------------------------------------------
__global__ __launch_bounds__(256) void rownorm_kernel(const float* __restrict__ A, int which) {
    int row = blockIdx.x * 32 + (threadIdx.x >> 3);
    int l = threadIdx.x & 7;
    const float4* a = (const float4*)(A + (size_t)row * DIM);
    float4 v1 = __ldg(&a[l * 2]);
    float4 v2 = __ldg(&a[l * 2 + 1]);
    float s = v1.x*v1.x + v1.y*v1.y + v1.z*v1.z + v1.w*v1.w
            + v2.x*v2.x + v2.y*v2.y + v2.z*v2.z + v2.w*v2.w;
    s += __shfl_down_sync(0xffffffffu, s, 4);
    s += __shfl_down_sync(0xffffffffu, s, 2);
    s += __shfl_down_sync(0xffffffffu, s, 1);
    if (l == 0) {
        float* out = which ? g_y2 : g_x2;
        out[row] = s;
    }
}

// ---------------------------------------------------------------------------
// Kernel 1: pairwise squared distances with packed f32x2 FFMA2.
// Writes TRANSPOSED + log2e-scaled: D_t[b][j][i] = log2e*(x2[i]+y2[j]-2*dot).
// Epilogue: smem-staged transpose (4 chunks of 32 columns) -> coalesced STG.
// ---------------------------------------------------------------------------
#define BM 128
#define BN 128
#define BK 16
#define STRX 34
#define STRY 34
#define TPAD 132

__global__ __launch_bounds__(256, 2) void pairdist_kernel(const float* __restrict__ X,
                                                          const float* __restrict__ Y) {
    __shared__ __align__(16) float Xs2[BM * STRX];
    __shared__ float Ys2[64 * STRY];

    int b  = blockIdx.z;
    int i0 = blockIdx.y * BM;
    int j0 = blockIdx.x * BN;
    const float* Xb = X + (size_t)b * SEQ * DIM + (size_t)i0 * DIM;
    const float* Yb = Y + (size_t)b * SEQ * DIM + (size_t)j0 * DIM;

    int tid = threadIdx.x;
    int tx = tid & 15;
    int ty = tid >> 4;

    u64 acc2[8][4];
#pragma unroll
    for (int r = 0; r < 8; r++)
#pragma unroll
        for (int c2 = 0; c2 < 4; c2++) acc2[r][c2] = 0ull;

    for (int k0 = 0; k0 < DIM; k0 += BK) {
        __syncthreads();
#pragma unroll
        for (int q = 0; q < 2; q++) {
            int idx = tid + q * 256;
            int r  = idx >> 2;
            int c4 = idx & 3;
            float4 xv = __ldg((const float4*)(Xb + (size_t)r * DIM + k0 + c4 * 4));
            float4 yv = __ldg((const float4*)(Yb + (size_t)r * DIM + k0 + c4 * 4));
            u64* xs = (u64*)&Xs2[r * STRX + c4 * 8];
            xs[0] = pack2(xv.x, xv.x);
            xs[1] = pack2(xv.y, xv.y);
            xs[2] = pack2(xv.z, xv.z);
            xs[3] = pack2(xv.w, xv.w);
            int pr   = (r & 15) + 16 * (r >> 5);
            int slot = (r >> 4) & 1;
            float* ys = &Ys2[pr * STRY + c4 * 8 + slot];
            ys[0] = yv.x; ys[2] = yv.y; ys[4] = yv.z; ys[6] = yv.w;
        }
        __syncthreads();

#pragma unroll
        for (int k = 0; k < BK; k++) {
            u64 bb[4];
#pragma unroll
            for (int c2 = 0; c2 < 4; c2++)
                bb[c2] = *(const u64*)&Ys2[(tx + 16 * c2) * STRY + k * 2];
#pragma unroll
            for (int r = 0; r < 8; r++) {
                u64 aa = *(const u64*)&Xs2[(ty + 16 * r) * STRX + k * 2];
#pragma unroll
                for (int c2 = 0; c2 < 4; c2++)
                    acc2[r][c2] = ffma2(aa, bb[c2], acc2[r][c2]);
            }
        }
    }

    // -------- epilogue: finalize + transpose via smem + coalesced store -----
    float yn[8];
#pragma unroll
    for (int c = 0; c < 8; c++) yn[c] = g_y2[b * SEQ + j0 + tx + 16 * c];
    float xnr[8];
#pragma unroll
    for (int r = 0; r < 8; r++) xnr[r] = g_x2[b * SEQ + i0 + ty + 16 * r];

    float* Dt = g_D + (size_t)b * SEQ * SEQ;
    float* T  = Xs2;

    __syncthreads();
#pragma unroll
    for (int q = 0; q < 4; q++) {
#pragma unroll
        for (int r = 0; r < 8; r++) {
            int ii = ty + 16 * r;
            float2 d2 = unpack2(acc2[r][q]);
            T[tx * TPAD + ii]        = LOG2E * (xnr[r] + yn[2 * q]     - 2.0f * d2.x);
            T[(tx + 16) * TPAD + ii] = LOG2E * (xnr[r] + yn[2 * q + 1] - 2.0f * d2.y);
        }
        __syncthreads();
#pragma unroll
        for (int v = 0; v < 4; v++) {
            int jj2 = tid >> 3;
            int ii2 = (tid & 7) * 16 + v * 4;
            float4 t = *(float4*)&T[jj2 * TPAD + ii2];
            *(float4*)&Dt[(size_t)(j0 + 32 * q + jj2) * SEQ + i0 + ii2] = t;
        }
        __syncthreads();
    }
}

// ---------------------------------------------------------------------------
// Kernel 2: soft-DTW, sync-free, one warp/batch, 16 rows/lane.
// FAST PATH = pure hard-min (no MUFU, no setp on chain): chain 12 cyc/cell.
// Exact gap-to-second detector: sec = fmin(fmax(a,lo),hi); trigger iff
// sec - mn < 8 (log2 domain; P ~ 1e-7/cell for this data; boundary +-BIGF
// cases provably don't trigger). Fallback: full-softmin recompute of the
// 16-cell column (exact), amortized cost ~0.
// Steady region (beats 33..509): all lanes active -> NO guard branch.
// Prefetch: unconditional, index clamped to [0, SEQ-1] (no divergence).
// Banks: 3-way loop unroll -> static rotation (no MOVs, no dynamic indexing).
// Bank init: bank s = column max(s - lane, 0); banks a lane activates on
// before 3 prefetch beats elapse get exactly cols 0,1,2 (verified per-lane).
// ---------------------------------------------------------------------------
#define FCELL(NV, VOLD, DV) {                                        \
    float l_ = (VOLD); float lo_ = fminf(u, l_), hi_ = fmaxf(u, l_); \
    float mn_ = fminf(a, lo_), m1_ = fmaxf(a, lo_);                  \
    gmin = fminf(gmin, fminf(m1_, hi_) - mn_);                       \
    NV = (DV) + mn_; a = l_; u = NV; }

#define XCELL(NV, VOLD, DV) {                                        \
    float l_ = (VOLD); float lo_ = fminf(u, l_), hi_ = fmaxf(u, l_); \
    float mn_ = fminf(a, lo_), m1_ = fmaxf(a, lo_);                  \
    float s_ = 1.0f + ex2(mn_ - m1_) + ex2(mn_ - hi_);               \
    NV = (DV) + mn_ - lg2(s_); a = l_; u = NV; }

#define ALL16(M, Ca, Cb, Cc, Cd)                                     \
    M(nv0,  v0,  Ca.x) M(nv1,  v1,  Ca.y) M(nv2,  v2,  Ca.z) M(nv3,  v3,  Ca.w) \
    M(nv4,  v4,  Cb.x) M(nv5,  v5,  Cb.y) M(nv6,  v6,  Cb.z) M(nv7,  v7,  Cb.w) \
    M(nv8,  v8,  Cc.x) M(nv9,  v9,  Cc.y) M(nv10, v10, Cc.z) M(nv11, v11, Cc.w) \
    M(nv12, v12, Cd.x) M(nv13, v13, Cd.y) M(nv14, v14, Cd.z) M(nv15, v15, Cd.w)

#define COMMIT16() { v0=nv0; v1=nv1; v2=nv2; v3=nv3; v4=nv4; v5=nv5; v6=nv6;   \
    v7=nv7; v8=nv8; v9=nv9; v10=nv10; v11=nv11; v12=nv12; v13=nv13; v14=nv14;  \
    v15=nv15; }

#define BEAT(IDX, Ca, Cb, Cc, Cd, GUARDED) {                                   \
    float sh = __shfl_up_sync(0xffffffffu, v15, 1);                            \
    if (lane == 0) sh = BIGF;                                                  \
    int j_ = (IDX) - lane;                                                     \
    if (!(GUARDED) || (j_ >= 0 && j_ < SEQ)) {                                 \
        float a = shp, u = sh, gmin = BIGF;                                    \
        ALL16(FCELL, Ca, Cb, Cc, Cd)                                           \
        if (gmin < 8.0f) { a = shp; u = sh; ALL16(XCELL, Ca, Cb, Cc, Cd) }     \
        COMMIT16()                                                             \
        if ((GUARDED) && lane == 31 && j_ == SEQ - 1) out[b] = v15 * LN2;      \
    }                                                                          \
    shp = sh;                                                                  \
    { int jp = (IDX) - lane + 3;                                               \
      jp = jp < 0 ? 0 : jp; jp = jp > SEQ - 1 ? SEQ - 1 : jp;                  \
      const float4* p_ = colbase + (size_t)jp * CSTRIDE;                       \
      Ca = __ldg(p_); Cb = __ldg(p_ + 1); Cc = __ldg(p_ + 2); Cd = __ldg(p_ + 3); } }

__global__ __launch_bounds__(32, 1) void softdtw_kernel(float* __restrict__ out) {
    int b    = blockIdx.x;
    int lane = threadIdx.x;

    const float4* colbase = (const float4*)(g_D + (size_t)b * SEQ * SEQ + lane * 16);
    const int CSTRIDE = SEQ / 4;

    float v0=BIGF,v1=BIGF,v2=BIGF,v3=BIGF,v4=BIGF,v5=BIGF,v6=BIGF,v7=BIGF,
          v8=BIGF,v9=BIGF,v10=BIGF,v11=BIGF,v12=BIGF,v13=BIGF,v14=BIGF,v15=BIGF;
    float nv0,nv1,nv2,nv3,nv4,nv5,nv6,nv7,nv8,nv9,nv10,nv11,nv12,nv13,nv14,nv15;
    float shp = (lane == 0) ? 0.0f : BIGF;   // R(16*lane-1, j-1); (0,0) diag = 0

    // bank init: bank s holds column max(s - lane, 0)
    int e1 = 1 - lane; e1 = e1 < 0 ? 0 : e1;
    int e2 = 2 - lane; e2 = e2 < 0 ? 0 : e2;
    const float4* p0 = colbase;
    const float4* p1 = colbase + (size_t)e1 * CSTRIDE;
    const float4* p2 = colbase + (size_t)e2 * CSTRIDE;
    float4 P0=__ldg(p0),P1=__ldg(p0+1),P2=__ldg(p0+2),P3=__ldg(p0+3);
    float4 Q0=__ldg(p1),Q1=__ldg(p1+1),Q2=__ldg(p1+2),Q3=__ldg(p1+3);
    float4 R0=__ldg(p2),R1=__ldg(p2+1),R2=__ldg(p2+2),R3=__ldg(p2+3);

    int idx = 0;
    // warm-up: beats 0..32 (guarded)
#pragma unroll 1
    for (int t = 0; t < 11; t++) {
        BEAT(idx,     P0, P1, P2, P3, 1)
        BEAT(idx + 1, Q0, Q1, Q2, Q3, 1)
        BEAT(idx + 2, R0, R1, R2, R3, 1)
        idx += 3;
    }
    // steady: beats 33..509 (all lanes active, NO guard)
#pragma unroll 1
    for (int t = 0; t < 159; t++) {
        BEAT(idx,     P0, P1, P2, P3, 0)
        BEAT(idx + 1, Q0, Q1, Q2, Q3, 0)
        BEAT(idx + 2, R0, R1, R2, R3, 0)
        idx += 3;
    }
    // tail: beats 510..542 (guarded; final output at idx=542, lane 31)
#pragma unroll 1
    for (int t = 0; t < 11; t++) {
        BEAT(idx,     P0, P1, P2, P3, 1)
        BEAT(idx + 1, Q0, Q1, Q2, Q3, 1)
        BEAT(idx + 2, R0, R1, R2, R3, 1)
        idx += 3;
    }
}

// ---------------------------------------------------------------------------
extern "C" void kernel_launch(void* const* d_in, const int* in_sizes, int n_in,
                              void* d_out, int out_size) {
    const float* x = (const float*)d_in[0];
    const float* y = (const float*)d_in[1];
    float* out = (float*)d_out;

    rownorm_kernel<<<NB * SEQ / 32, 256>>>(x, 0);
    rownorm_kernel<<<NB * SEQ / 32, 256>>>(y, 1);

    dim3 g(SEQ / BN, SEQ / BM, NB);
    pairdist_kernel<<<g, 256>>>(x, y);

    softdtw_kernel<<<NB, 32>>>(out);
}